// round 14
// baseline (speedup 1.0000x reference)
#include <cuda_runtime.h>
#include <cstdint>

// Linear-chain CRF log-partition, B=64, T=4096, S=64.
// Strategy: log-space scan rewritten as linear-space 64x64 matvec per step with
// running log-offset. exp(transition) precomputed once. One warp = 2 batches,
// ET column-pair in registers (f32x2), packed FFMA2 mainloop, p shared via
// double-buffered smem with a single __syncwarp per step.

typedef unsigned long long ull;

__device__ __forceinline__ ull fma2(ull a, ull b, ull c) {
    ull d;
    asm("fma.rn.f32x2 %0, %1, %2, %3;" : "=l"(d) : "l"(a), "l"(b), "l"(c));
    return d;
}
__device__ __forceinline__ ull add2(ull a, ull b) {
    ull d;
    asm("add.rn.f32x2 %0, %1, %2;" : "=l"(d) : "l"(a), "l"(b));
    return d;
}
__device__ __forceinline__ void upk2(ull v, float& x, float& y) {
    asm("mov.b64 {%0, %1}, %2;" : "=f"(x), "=f"(y) : "l"(v));
}

static __device__ float g_ET[64 * 64];  // exp(transition), computed by prep kernel

__global__ void crf_expT_kernel(const float* __restrict__ T) {
    int i = blockIdx.x * blockDim.x + threadIdx.x;
    if (i < 64 * 64) g_ET[i] = expf(T[i]);
}

__global__ __launch_bounds__(32, 1)
void crf_scan_kernel(const float* __restrict__ scores,
                     const float* __restrict__ source,
                     const float* __restrict__ sink,
                     float* __restrict__ out) {
    const int lane = threadIdx.x;
    const int b0 = blockIdx.x * 2;
    const int b1 = b0 + 1;

    // p duplicated-packed {p,p} per state, double-buffered, per batch
    __shared__ float4 pd[2][2][32];  // [buf][batch][lane] = {px,px,py,py}

    // ET column pair for states j=2*lane, 2*lane+1: et[i] = {ET[i][2l], ET[i][2l+1]}
    ull et[64];
#pragma unroll
    for (int i = 0; i < 64; ++i)
        et[i] = *reinterpret_cast<const ull*>(&g_ET[i * 64 + 2 * lane]);

    const float* sp0 = scores + ((long)b0 * 4096) * 64 + 2 * lane;
    const float* sp1 = scores + ((long)b1 * 4096) * 64 + 2 * lane;

    const float2 src = *reinterpret_cast<const float2*>(source + 2 * lane);
    const float LOGS = 4.1588830833596715f;  // log(64), reproduces reference's t==0 constant

    float2 e0a = *reinterpret_cast<const float2*>(sp0);
    float2 e0b = *reinterpret_cast<const float2*>(sp1);
    float aAx = src.x + e0a.x + LOGS, aAy = src.y + e0a.y + LOGS;
    float aBx = src.x + e0b.x + LOGS, aBy = src.y + e0b.y + LOGS;
    float CA = 0.0f, CB = 0.0f;

    // 2-step-ahead emission prefetch
    float2 sA[2], sB[2];
    sA[0] = *reinterpret_cast<const float2*>(sp0 + 64);
    sA[1] = *reinterpret_cast<const float2*>(sp0 + 128);
    sB[0] = *reinterpret_cast<const float2*>(sp1 + 64);
    sB[1] = *reinterpret_cast<const float2*>(sp1 + 128);

    int buf = 0;
    for (int t = 1; t < 4096; ++t) {
        const int slot = (t - 1) & 1;

        // ---- serial phase: normalize, exponentiate, publish p ----
        float mA = __shfl_sync(0xffffffffu, aAx, 0);
        float mB = __shfl_sync(0xffffffffu, aBx, 0);
        CA += mA;
        CB += mB;
        float pAx = __expf(aAx - mA), pAy = __expf(aAy - mA);
        float pBx = __expf(aBx - mB), pBy = __expf(aBy - mB);
        pd[buf][0][lane] = make_float4(pAx, pAx, pAy, pAy);
        pd[buf][1][lane] = make_float4(pBx, pBx, pBy, pBy);
        __syncwarp();

        // current emissions + refill prefetch slot (t+2, clamped)
        const float2 scA = sA[slot];
        const float2 scB = sB[slot];
        int tp = t + 2;
        if (tp > 4095) tp = 4095;
        sA[slot] = *reinterpret_cast<const float2*>(sp0 + (long)tp * 64);
        sB[slot] = *reinterpret_cast<const float2*>(sp1 + (long)tp * 64);

        // ---- matvec: v[j] = sum_i p[i] * ET[i][j], packed over the two j's ----
        const longlong2* pA4 = reinterpret_cast<const longlong2*>(&pd[buf][0][0]);
        const longlong2* pB4 = reinterpret_cast<const longlong2*>(&pd[buf][1][0]);
        ull aa0 = 0, aa1 = 0, ab0 = 0, ab1 = 0;
#pragma unroll
        for (int k = 0; k < 32; ++k) {
            longlong2 qa = pA4[k];
            longlong2 qb = pB4[k];
            aa0 = fma2((ull)qa.x, et[2 * k], aa0);
            ab0 = fma2((ull)qb.x, et[2 * k], ab0);
            aa1 = fma2((ull)qa.y, et[2 * k + 1], aa1);
            ab1 = fma2((ull)qb.y, et[2 * k + 1], ab1);
        }
        float vAx, vAy, vBx, vBy;
        upk2(add2(aa0, aa1), vAx, vAy);
        upk2(add2(ab0, ab1), vBx, vBy);

        aAx = __logf(vAx) + scA.x;
        aAy = __logf(vAy) + scA.y;
        aBx = __logf(vBx) + scB.x;
        aBy = __logf(vBy) + scB.y;

        buf ^= 1;
    }

    // ---- epilogue: out[b] = C + logsumexp_j(alpha[j] + sink[j]) ----
    const float2 snk = *reinterpret_cast<const float2*>(sink + 2 * lane);
    float tA0 = aAx + snk.x, tA1 = aAy + snk.y;
    float tB0 = aBx + snk.x, tB1 = aBy + snk.y;
    float mA = fmaxf(tA0, tA1), mB = fmaxf(tB0, tB1);
#pragma unroll
    for (int o = 16; o; o >>= 1) {
        mA = fmaxf(mA, __shfl_xor_sync(0xffffffffu, mA, o));
        mB = fmaxf(mB, __shfl_xor_sync(0xffffffffu, mB, o));
    }
    float suA = expf(tA0 - mA) + expf(tA1 - mA);
    float suB = expf(tB0 - mB) + expf(tB1 - mB);
#pragma unroll
    for (int o = 16; o; o >>= 1) {
        suA += __shfl_xor_sync(0xffffffffu, suA, o);
        suB += __shfl_xor_sync(0xffffffffu, suB, o);
    }
    if (lane == 0) {
        out[b0] = CA + mA + logf(suA);
        out[b1] = CB + mB + logf(suB);
    }
}

extern "C" void kernel_launch(void* const* d_in, const int* in_sizes, int n_in,
                              void* d_out, int out_size) {
    (void)in_sizes; (void)n_in; (void)out_size;
    const float* scores     = (const float*)d_in[0];  // (64, 4096, 64)
    const float* transition = (const float*)d_in[1];  // (64, 64)
    const float* source     = (const float*)d_in[2];  // (64,)
    const float* sink       = (const float*)d_in[3];  // (64,)
    float* out = (float*)d_out;                       // (64,)

    crf_expT_kernel<<<8, 512>>>(transition);
    crf_scan_kernel<<<32, 32>>>(scores, source, sink, out);
}

// round 15
// speedup vs baseline: 1.8548x; 1.8548x over previous
#include <cuda_runtime.h>
#include <cstdint>

// Linear-chain CRF log-partition, B=64, T=4096, S=64.
// Linear-space scan: v' = (v @ expT) * exp(s_t) with per-step power-of-2
// renormalization (exponent-field integer math, exact ksum accumulation).
// One warp per batch; exp(transition) columns in registers as f32x2;
// emissions exp() pipelined off the critical path.

typedef unsigned long long ull;

__device__ __forceinline__ ull fma2(ull a, ull b, ull c) {
    ull d;
    asm("fma.rn.f32x2 %0, %1, %2, %3;" : "=l"(d) : "l"(a), "l"(b), "l"(c));
    return d;
}
__device__ __forceinline__ ull add2(ull a, ull b) {
    ull d;
    asm("add.rn.f32x2 %0, %1, %2;" : "=l"(d) : "l"(a), "l"(b));
    return d;
}
__device__ __forceinline__ void upk2(ull v, float& x, float& y) {
    asm("mov.b64 {%0, %1}, %2;" : "=f"(x), "=f"(y) : "l"(v));
}

static __device__ float g_ET[64 * 64];  // exp(transition)

__global__ void crf_expT_kernel(const float* __restrict__ T) {
    int i = blockIdx.x * blockDim.x + threadIdx.x;
    if (i < 64 * 64) g_ET[i] = expf(T[i]);
}

__global__ __launch_bounds__(32, 1)
void crf_scan_kernel(const float* __restrict__ scores,
                     const float* __restrict__ source,
                     const float* __restrict__ sink,
                     float* __restrict__ out) {
    const int lane = threadIdx.x;
    const int b = blockIdx.x;

    __shared__ float4 pd[32];  // pd[lane] = {vx, vx, vy, vy} (duplicated-packed)

    // ET column pair for states j=2*lane, 2*lane+1: et[i] = {ET[i][2l], ET[i][2l+1]}
    ull et[64];
#pragma unroll
    for (int i = 0; i < 64; ++i)
        et[i] = *reinterpret_cast<const ull*>(&g_ET[i * 64 + 2 * lane]);

    const float* sp = scores + ((long)b * 4096) * 64 + 2 * lane;

    const float2 src = *reinterpret_cast<const float2*>(source + 2 * lane);
    const float2 e0 = *reinterpret_cast<const float2*>(sp);
    float a0x = src.x + e0.x, a0y = src.y + e0.y;
    float m0 = __shfl_sync(0xffffffffu, a0x, 0);
    float vx = __expf(a0x - m0);
    float vy = __expf(a0y - m0);
    int ksum = 0;

    // emission pipeline: eCur = exp(s_1), sPre = s_2
    float2 s1 = *reinterpret_cast<const float2*>(sp + 64);
    float2 eCur = make_float2(__expf(s1.x), __expf(s1.y));
    float2 sPre = *reinterpret_cast<const float2*>(sp + 128);

#pragma unroll 1
    for (int t = 1; t < 4096; ++t) {
        // publish (unscaled) v for the all-to-all matvec
        pd[lane] = make_float4(vx, vx, vy, vy);
        float mval = __shfl_sync(0xffffffffu, vx, 0);  // normalizer (off matvec path)
        __syncwarp();

        const float2 emis = eCur;
        // refill pipeline: load s_{t+2}, exp s_{t+1}
        int tp = t + 2;
        if (tp > 4095) tp = 4095;
        float2 sNew = *reinterpret_cast<const float2*>(sp + (long)tp * 64);
        eCur = make_float2(__expf(sPre.x), __expf(sPre.y));
        sPre = sNew;

        // power-of-2 renormalization from lane-0 exponent (integer ops, exact)
        int k = ((__float_as_int(mval) >> 23) & 0xff) - 127;
        ksum += k;
        float sc = __int_as_float((127 - k) << 23);  // 2^-k

        // matvec: v'[j] = sum_i v[i] * ET[i][j], 4 independent packed chains
        const longlong2* p4 = reinterpret_cast<const longlong2*>(pd);
        ull A0 = 0, A1 = 0, A2 = 0, A3 = 0;
#pragma unroll
        for (int kk = 0; kk < 16; ++kk) {
            longlong2 q = p4[kk];
            longlong2 r = p4[kk + 16];
            A0 = fma2((ull)q.x, et[2 * kk], A0);
            A1 = fma2((ull)q.y, et[2 * kk + 1], A1);
            A2 = fma2((ull)r.x, et[2 * kk + 32], A2);
            A3 = fma2((ull)r.y, et[2 * kk + 33], A3);
        }
        float sx, sy;
        upk2(add2(add2(A0, A1), add2(A2, A3)), sx, sy);

        vx = sx * (emis.x * sc);
        vy = sy * (emis.y * sc);
    }

    // epilogue: out[b] = ksum*ln2 + m0 + log(64) + logsumexp_j(log v_j + sink_j)
    const float2 snk = *reinterpret_cast<const float2*>(sink + 2 * lane);
    float t0 = logf(vx) + snk.x;   // logf(0) = -inf handled by fmax/exp
    float t1 = logf(vy) + snk.y;
    float m = fmaxf(t0, t1);
#pragma unroll
    for (int o = 16; o; o >>= 1)
        m = fmaxf(m, __shfl_xor_sync(0xffffffffu, m, o));
    float su = expf(t0 - m) + expf(t1 - m);
#pragma unroll
    for (int o = 16; o; o >>= 1)
        su += __shfl_xor_sync(0xffffffffu, su, o);

    if (lane == 0) {
        double off = (double)ksum * 0.6931471805599453 +
                     (double)m0 + 4.1588830833596715;  // + log(64) (reference quirk)
        out[b] = (float)(off + (double)(m + logf(su)));
    }
}

extern "C" void kernel_launch(void* const* d_in, const int* in_sizes, int n_in,
                              void* d_out, int out_size) {
    (void)in_sizes; (void)n_in; (void)out_size;
    const float* scores     = (const float*)d_in[0];  // (64, 4096, 64)
    const float* transition = (const float*)d_in[1];  // (64, 64)
    const float* source     = (const float*)d_in[2];  // (64,)
    const float* sink       = (const float*)d_in[3];  // (64,)
    float* out = (float*)d_out;                       // (64,)

    crf_expT_kernel<<<8, 512>>>(transition);
    crf_scan_kernel<<<64, 32>>>(scores, source, sink, out);
}